// round 6
// baseline (speedup 1.0000x reference)
#include <cuda_runtime.h>
#include <math.h>

// predicts/targets (2,4,64,256,256) f32, masks (2,1,64,256,256) f32 -> scalar f32.
//
// Identities (validated R2/R3, rel_err ~1e-7):
//   omega_pred - omega_trgt = vorticity(scale*(P-T))   [linearity, shared mask]
//   scale(10) / (2*delta=10) = 1 -> omega = raw neighbor diffs of d = P-T
//   voxel counts & contributes <=> all 27 masks in 3x3x3 neighborhood == 1
namespace {
constexpr int Bn = 2, Cn = 4, Dn = 64, Hn = 256, Wn = 256;
constexpr long long CH   = (long long)Dn * Hn * Wn;    // channel volume (elems)
constexpr int WORDS_ROW  = Wn / 32;                    // 8 words per x-row
constexpr int NROWS      = Bn * Dn * Hn;               // 32768 rows
constexpr int NBITWORDS  = NROWS * WORDS_ROW;          // 262144 words (1 MB)
constexpr int GY = Hn - 2;                             // 254
constexpr int GZ = Bn * (Dn - 2);                      // 124
constexpr int NBLK = GY * GZ;                          // 31496 partials
}

__device__ unsigned int g_bits[NBITWORDS];
__device__ float        g_psum[NBLK];
__device__ unsigned int g_pcnt[NBLK];

// ---- Pass 1: pack mask (0.0/1.0 floats) into 1 bit/voxel. Fully coalesced. ----
__global__ __launch_bounds__(256)
void k_pack(const float* __restrict__ M) {
    const int idx  = blockIdx.x * 256 + threadIdx.x;       // voxel index
    const unsigned bal = __ballot_sync(0xffffffffu, M[idx] > 0.5f);
    if ((threadIdx.x & 31) == 0) g_bits[idx >> 5] = bal;
}

// ---- Pass 2: one block per interior row (b, z, y); 256 threads = full x-row. ----
__global__ __launch_bounds__(256, 8)
void k_main(const float* __restrict__ P,
            const float* __restrict__ T) {
    const int x  = threadIdx.x;            // 0..255
    const int y  = blockIdx.x + 1;         // 1..254
    const int bz = blockIdx.y;
    const int b  = bz / (Dn - 2);
    const int z  = bz % (Dn - 2) + 1;      // 1..62

    // Stage the 9 neighbor bit-rows (3z x 3y), then AND word-wise -> A[8].
    __shared__ unsigned int Wd[9][WORDS_ROW];
    __shared__ unsigned int A[WORDS_ROW];
    if (threadIdx.x < 9 * WORDS_ROW) {
        const int r  = threadIdx.x >> 3;               // 0..8  (dz*3+dy)
        const int j  = threadIdx.x & 7;                // word in row
        const int zz = z - 1 + r / 3;
        const int yy = y - 1 + r % 3;
        const int row = (b * Dn + zz) * Hn + yy;
        Wd[r][j] = g_bits[row * WORDS_ROW + j];
    }
    __syncthreads();
    if (threadIdx.x < WORDS_ROW) {
        unsigned a = Wd[0][threadIdx.x];
        #pragma unroll
        for (int r = 1; r < 9; ++r) a &= Wd[r][threadIdx.x];
        A[threadIdx.x] = a;
    }
    __syncthreads();

    float s = 0.f;
    int   c = 0;
    if (x >= 1 && x <= Wn - 2) {
        const unsigned bl = (A[(x - 1) >> 5] >> ((x - 1) & 31)) & 1u;
        const unsigned bc = (A[x       >> 5] >> (x       & 31)) & 1u;
        const unsigned br = (A[(x + 1) >> 5] >> ((x + 1) & 31)) & 1u;
        if (bl & bc & br) {                                   // 27-AND holds
            c = 1;
            const float* Pu = P + ((long long)b * Cn + 1) * CH;
            const float* Tu = T + ((long long)b * Cn + 1) * CH;
            const float* Pv = Pu + CH;  const float* Tv = Tu + CH;
            const float* Pw = Pv + CH;  const float* Tw = Tv + CH;

            const long long i  = ((long long)z * Hn + y) * Wn + x;
            const long long zp = i + (long long)Hn * Wn;
            const long long zm = i - (long long)Hn * Wn;
            const long long yp = i + Wn;
            const long long ym = i - Wn;

            const float ox = ((Pw[yp] - Tw[yp]) - (Pw[ym] - Tw[ym]))
                           - ((Pv[zp] - Tv[zp]) - (Pv[zm] - Tv[zm]));
            const float oy = ((Pu[zp] - Tu[zp]) - (Pu[zm] - Tu[zm]))
                           - ((Pw[i + 1] - Tw[i + 1]) - (Pw[i - 1] - Tw[i - 1]));
            const float oz = ((Pv[i + 1] - Tv[i + 1]) - (Pv[i - 1] - Tv[i - 1]))
                           - ((Pu[yp] - Tu[yp]) - (Pu[ym] - Tu[ym]));

            s = sqrtf(ox * ox + oy * oy + oz * oz);
        }
    }

    // Block reduction -> one unconditional partial per block (no atomics, no zeroing).
    #pragma unroll
    for (int off = 16; off; off >>= 1) {
        s += __shfl_down_sync(0xffffffffu, s, off);
        c += __shfl_down_sync(0xffffffffu, c, off);
    }
    __shared__ float ws[8];
    __shared__ int   wc[8];
    const int wid = threadIdx.x >> 5, lid = threadIdx.x & 31;
    if (lid == 0) { ws[wid] = s; wc[wid] = c; }
    __syncthreads();
    if (wid == 0) {
        s = (lid < 8) ? ws[lid] : 0.f;
        c = (lid < 8) ? wc[lid] : 0;
        #pragma unroll
        for (int off = 4; off; off >>= 1) {
            s += __shfl_down_sync(0xffffffffu, s, off);
            c += __shfl_down_sync(0xffffffffu, c, off);
        }
        if (lid == 0) {
            const int slot = blockIdx.y * GY + blockIdx.x;
            g_psum[slot] = s;
            g_pcnt[slot] = (unsigned)c;
        }
    }
}

// ---- Pass 3: reduce 31496 partials; double accumulation; scalar out. ----
__global__ __launch_bounds__(1024)
void k_final(float* __restrict__ out) {
    const int tid = threadIdx.x;
    double             s = 0.0;
    unsigned long long c = 0ull;
    for (int i = tid; i < NBLK; i += 1024) {
        s += (double)g_psum[i];
        c += (unsigned long long)g_pcnt[i];
    }
    #pragma unroll
    for (int off = 16; off; off >>= 1) {
        s += __shfl_down_sync(0xffffffffu, s, off);
        c += __shfl_down_sync(0xffffffffu, c, off);
    }
    __shared__ double             ds[32];
    __shared__ unsigned long long dc[32];
    const int wid = tid >> 5, lid = tid & 31;
    if (lid == 0) { ds[wid] = s; dc[wid] = c; }
    __syncthreads();
    if (wid == 0) {
        s = (lid < 32) ? ds[lid] : 0.0;
        c = (lid < 32) ? dc[lid] : 0ull;
        #pragma unroll
        for (int off = 16; off; off >>= 1) {
            s += __shfl_down_sync(0xffffffffu, s, off);
            c += __shfl_down_sync(0xffffffffu, c, off);
        }
        if (lid == 0) out[0] = (float)(s / (double)c);
    }
}

extern "C" void kernel_launch(void* const* d_in, const int* in_sizes, int n_in,
                              void* d_out, int out_size) {
    const float* P = (const float*)d_in[0];
    const float* T = (const float*)d_in[1];
    const float* M = (const float*)d_in[2];
    float*       O = (float*)d_out;

    k_pack<<<(Bn * (int)CH) / 256, 256>>>(M);
    k_main<<<dim3(GY, GZ), 256>>>(P, T);
    k_final<<<1, 1024>>>(O);
}

// round 7
// speedup vs baseline: 1.2377x; 1.2377x over previous
#include <cuda_runtime.h>
#include <math.h>

// predicts/targets (2,4,64,256,256) f32, masks (2,1,64,256,256) f32 -> scalar f32.
// Identities (validated R2..R5, rel_err ~1e-7):
//   omega_pred - omega_trgt = vorticity(scale*(P-T));  scale/(2*delta)=1
//   voxel counts & contributes <=> all 27 masks in 3x3x3 neighborhood == 1
// Streaming design: unconditional compute, every global load coalesced, y-rolling
// smem rings, one sync per row-step.
namespace {
constexpr int Bn = 2, Cn = 4, Dn = 64, Hn = 256, Wn = 256;
constexpr long long CH = (long long)Dn * Hn * Wn;
constexpr int YT  = 16;                 // output y-rows per block
constexpr int NYT = 16;                 // ceil(254/16)
constexpr int GZ  = Bn * (Dn - 2);      // 124
constexpr int NBLK = NYT * GZ;          // 1984 partials
}

__device__ float        g_psum[NBLK];
__device__ unsigned int g_pcnt[NBLK];

__global__ __launch_bounds__(256, 6)
void k_main(const float* __restrict__ P,
            const float* __restrict__ T,
            const float* __restrict__ M) {
    const int x  = threadIdx.x;                       // 0..255
    const int b  = blockIdx.y / (Dn - 2);
    const int z  = blockIdx.y % (Dn - 2) + 1;         // 1..62
    const int y0 = 1 + blockIdx.x * YT;
    const int y1 = min(y0 + YT - 1, Hn - 2);          // last tile has 14 rows

    // y-rolling rings (depth 4: depth 3 races across the single per-step sync)
    __shared__ float dU[4][Wn];   // (P-T) of u, z-plane, rows y-1..y+1
    __shared__ float dW[4][Wn];   // (P-T) of w, z-plane
    __shared__ float CP[4][Wn];   // mask column product m(z-1)*m(z)*m(z+1)
    __shared__ float dV[2][Wn];   // (P-T) of v, row y (x+-1 access), dbl-buffered

    const float* mb = M + (long long)b * CH;
    const float* uP = P + ((long long)b * Cn + 1) * CH;
    const float* uT = T + ((long long)b * Cn + 1) * CH;
    const float* vP = uP + CH;  const float* vT = uT + CH;
    const float* wP = vP + CH;  const float* wT = vT + CH;

    auto idx = [&](int zz, int yy) { return ((long long)zz * Hn + yy) * Wn + x; };

    // Prologue: fill ring rows y0-1 and y0 (all coalesced).
    #pragma unroll
    for (int k = 0; k < 2; ++k) {
        const int yy = y0 - 1 + k, sp = yy & 3;
        dU[sp][x] = uP[idx(z, yy)] - uT[idx(z, yy)];
        dW[sp][x] = wP[idx(z, yy)] - wT[idx(z, yy)];
        CP[sp][x] = mb[idx(z - 1, yy)] * mb[idx(z, yy)] * mb[idx(z + 1, yy)];
    }

    float fs  = 0.f;
    int   cnt = 0;

    for (int y = y0; y <= y1; ++y) {
        // ---- stage row y+1 into rings + transients (17 coalesced LDGs/thread) ----
        const int sp = (y + 1) & 3;
        dU[sp][x] = uP[idx(z, y + 1)] - uT[idx(z, y + 1)];
        dW[sp][x] = wP[idx(z, y + 1)] - wT[idx(z, y + 1)];
        CP[sp][x] = mb[idx(z - 1, y + 1)] * mb[idx(z, y + 1)] * mb[idx(z + 1, y + 1)];
        dV[y & 1][x] = vP[idx(z, y)] - vT[idx(z, y)];
        const float dzU = (uP[idx(z + 1, y)] - uT[idx(z + 1, y)])
                        - (uP[idx(z - 1, y)] - uT[idx(z - 1, y)]);
        const float dzV = (vP[idx(z + 1, y)] - vT[idx(z + 1, y)])
                        - (vP[idx(z - 1, y)] - vT[idx(z - 1, y)]);
        __syncthreads();

        // ---- consume (x = 1..254 are outputs) ----
        if (x >= 1 && x <= Wn - 2) {
            const int sm1 = (y - 1) & 3, s0 = y & 3, sp1 = (y + 1) & 3;
            const float ok = CP[sm1][x - 1] * CP[sm1][x] * CP[sm1][x + 1]
                           * CP[s0 ][x - 1] * CP[s0 ][x] * CP[s0 ][x + 1]
                           * CP[sp1][x - 1] * CP[sp1][x] * CP[sp1][x + 1];  // 27-AND
            const float dyU = dU[sp1][x] - dU[sm1][x];
            const float dyW = dW[sp1][x] - dW[sm1][x];
            const float dxW = dW[s0][x + 1] - dW[s0][x - 1];
            const float dxV = dV[y & 1][x + 1] - dV[y & 1][x - 1];

            const float ox = dyW - dzV;
            const float oy = dzU - dxW;
            const float oz = dxV - dyU;

            fs  += ok * sqrtf(ox * ox + oy * oy + oz * oz);
            cnt += (ok > 0.f);
        }
        // Next iter's smem writes hit ring slot (y+2)&3 / buffer (y+1)&1 -- disjoint
        // from this iter's read set {(y-1),y,(y+1)}&3 / y&1, so one sync/step is safe.
    }

    // ---- block reduction -> unconditional partial (no atomics, no zero pass) ----
    #pragma unroll
    for (int off = 16; off; off >>= 1) {
        fs  += __shfl_down_sync(0xffffffffu, fs,  off);
        cnt += __shfl_down_sync(0xffffffffu, cnt, off);
    }
    __shared__ float ws[8];
    __shared__ int   wc[8];
    const int wid = threadIdx.x >> 5, lid = threadIdx.x & 31;
    if (lid == 0) { ws[wid] = fs; wc[wid] = cnt; }
    __syncthreads();
    if (wid == 0) {
        fs  = (lid < 8) ? ws[lid] : 0.f;
        cnt = (lid < 8) ? wc[lid] : 0;
        #pragma unroll
        for (int off = 4; off; off >>= 1) {
            fs  += __shfl_down_sync(0xffffffffu, fs,  off);
            cnt += __shfl_down_sync(0xffffffffu, cnt, off);
        }
        if (lid == 0) {
            const int slot = blockIdx.y * NYT + blockIdx.x;
            g_psum[slot] = fs;
            g_pcnt[slot] = (unsigned)cnt;
        }
    }
}

__global__ __launch_bounds__(1024)
void k_final(float* __restrict__ out) {
    const int tid = threadIdx.x;
    double             s = 0.0;
    unsigned long long c = 0ull;
    for (int i = tid; i < NBLK; i += 1024) {
        s += (double)g_psum[i];
        c += (unsigned long long)g_pcnt[i];
    }
    #pragma unroll
    for (int off = 16; off; off >>= 1) {
        s += __shfl_down_sync(0xffffffffu, s, off);
        c += __shfl_down_sync(0xffffffffu, c, off);
    }
    __shared__ double             ds[32];
    __shared__ unsigned long long dc[32];
    const int wid = tid >> 5, lid = tid & 31;
    if (lid == 0) { ds[wid] = s; dc[wid] = c; }
    __syncthreads();
    if (wid == 0) {
        s = (lid < 32) ? ds[lid] : 0.0;
        c = (lid < 32) ? dc[lid] : 0ull;
        #pragma unroll
        for (int off = 16; off; off >>= 1) {
            s += __shfl_down_sync(0xffffffffu, s, off);
            c += __shfl_down_sync(0xffffffffu, c, off);
        }
        if (lid == 0) out[0] = (float)(s / (double)c);
    }
}

extern "C" void kernel_launch(void* const* d_in, const int* in_sizes, int n_in,
                              void* d_out, int out_size) {
    const float* P = (const float*)d_in[0];
    const float* T = (const float*)d_in[1];
    const float* M = (const float*)d_in[2];
    float*       O = (float*)d_out;

    k_main<<<dim3(NYT, GZ), 256>>>(P, T, M);
    k_final<<<1, 1024>>>(O);
}

// round 8
// speedup vs baseline: 1.4635x; 1.1825x over previous
#include <cuda_runtime.h>
#include <math.h>

// predicts/targets (2,4,64,256,256) f32, masks (2,1,64,256,256) f32 -> scalar f32.
// Identities (validated R2..R6, rel_err ~1e-7):
//   omega_pred - omega_trgt = vorticity(scale*(P-T));  scale/(2*delta)=1
//   voxel counts & contributes <=> all 27 masks in 3x3x3 neighborhood == 1
namespace {
constexpr int Bn = 2, Cn = 4, Dn = 64, Hn = 256, Wn = 256;
constexpr long long CH = (long long)Dn * Hn * Wn;
constexpr int TY  = 6;                  // output rows per block
constexpr int RWS = 8;                  // staged rows (TY + 2 halo)
constexpr int NYT = 43;                 // ceil(254/6)
constexpr int ZC  = 3;                  // z-chunks: 21,21,20 interior planes
constexpr int NBLK = NYT * 2 * ZC;      // 258 partials
constexpr int PLF = RWS * Wn;           // elems per staged plane (2048)
// dynamic smem layout (bytes)
constexpr int OFF_U  = 0;                      // 4 f32 planes (z-ring)
constexpr int OFF_V  = OFF_U  + 4 * PLF * 4;   // 4 f32 planes
constexpr int OFF_W  = OFF_V  + 4 * PLF * 4;   // 3 f32 planes
constexpr int OFF_M  = OFF_W  + 3 * PLF * 4;   // 4 u8 planes (mask bits)
constexpr int OFF_CP = OFF_M  + 4 * PLF;       // 2 u8 planes (3z column AND)
constexpr int SMEM_BYTES = OFF_CP + 2 * PLF;   // 102400 B
}

__device__ float        g_psum[NBLK];
__device__ unsigned int g_pcnt[NBLK];

__global__ __launch_bounds__(256, 2)
void k_main(const float* __restrict__ P,
            const float* __restrict__ T,
            const float* __restrict__ M) {
    extern __shared__ unsigned char smem[];
    float*         sU  = (float*)(smem + OFF_U);
    float*         sV  = (float*)(smem + OFF_V);
    float*         sW  = (float*)(smem + OFF_W);
    unsigned char* sM  = smem + OFF_M;
    unsigned char* sCP = smem + OFF_CP;

    const int tid = threadIdx.x;
    const int b   = blockIdx.y / ZC;
    const int zi  = blockIdx.y % ZC;
    const int z0  = 1 + zi * 21;
    const int z1  = min(z0 + 20, Dn - 2);
    const int y0  = 1 + blockIdx.x * TY;

    const float* mb = M + (long long)b * CH;
    const float* uP = P + ((long long)b * Cn + 1) * CH;
    const float* uT = T + ((long long)b * Cn + 1) * CH;
    const float* vP = uP + CH;  const float* vT = uT + CH;
    const float* wP = vP + CH;  const float* wT = vT + CH;

    // ---- prologue: stage planes z0-1, z0 of u,v,m; plane z0 of w ----
    #pragma unroll
    for (int k = 0; k < 2; ++k) {
        const int zz = z0 - 1 + k;
        const int sf = zz & 3;                 // u,v,m ring slot
        #pragma unroll
        for (int i = 0; i < 2; ++i) {
            const int idx = (i << 8) | tid;
            const int r   = idx >> 6;          // 0..7
            const int x4  = (idx & 63) << 2;   // float4-aligned x
            const int yy  = min(y0 - 1 + r, Hn - 1);
            const long long base = ((long long)zz * Hn + yy) * Wn + x4;
            const int o = (sf * RWS + r) * Wn + x4;

            float4 a = *(const float4*)(uP + base);
            float4 c = *(const float4*)(uT + base);
            *(float4*)(sU + o) = make_float4(a.x - c.x, a.y - c.y, a.z - c.z, a.w - c.w);
            a = *(const float4*)(vP + base);
            c = *(const float4*)(vT + base);
            *(float4*)(sV + o) = make_float4(a.x - c.x, a.y - c.y, a.z - c.z, a.w - c.w);
            if (k == 1) {
                a = *(const float4*)(wP + base);
                c = *(const float4*)(wT + base);
                *(float4*)(sW + ((z0 % 3) * RWS + r) * Wn + x4)
                    = make_float4(a.x - c.x, a.y - c.y, a.z - c.z, a.w - c.w);
            }
            const float4 mv = *(const float4*)(mb + base);
            const unsigned mw = (mv.x > 0.5f ? 1u : 0u)
                              | (mv.y > 0.5f ? 1u : 0u) << 8
                              | (mv.z > 0.5f ? 1u : 0u) << 16
                              | (mv.w > 0.5f ? 1u : 0u) << 24;
            *(unsigned*)(sM + o) = mw;
        }
    }
    __syncthreads();

    float fs  = 0.f;
    int   cnt = 0;
    const int x = tid;

    for (int z = z0; z <= z1; ++z) {
        const int suN = (z + 1) & 3;           // new u/v/m slot
        const int szm = (z - 1) & 3, sz = z & 3;
        const int swz = z % 3, swN = (z + 1) % 3;
        const int scp = z & 1;

        // ---- stage plane z+1 (u,v,w,m) + compute CP(z) = AND of m(z-1..z+1) ----
        #pragma unroll
        for (int i = 0; i < 2; ++i) {
            const int idx = (i << 8) | tid;
            const int r   = idx >> 6;
            const int x4  = (idx & 63) << 2;
            const int yy  = min(y0 - 1 + r, Hn - 1);
            const long long base = ((long long)(z + 1) * Hn + yy) * Wn + x4;
            const int ro = r * Wn + x4;

            float4 a = *(const float4*)(uP + base);
            float4 c = *(const float4*)(uT + base);
            *(float4*)(sU + suN * PLF + ro) = make_float4(a.x - c.x, a.y - c.y, a.z - c.z, a.w - c.w);
            a = *(const float4*)(vP + base);
            c = *(const float4*)(vT + base);
            *(float4*)(sV + suN * PLF + ro) = make_float4(a.x - c.x, a.y - c.y, a.z - c.z, a.w - c.w);
            a = *(const float4*)(wP + base);
            c = *(const float4*)(wT + base);
            *(float4*)(sW + swN * PLF + ro) = make_float4(a.x - c.x, a.y - c.y, a.z - c.z, a.w - c.w);

            const float4 mv = *(const float4*)(mb + base);
            const unsigned mw = (mv.x > 0.5f ? 1u : 0u)
                              | (mv.y > 0.5f ? 1u : 0u) << 8
                              | (mv.z > 0.5f ? 1u : 0u) << 16
                              | (mv.w > 0.5f ? 1u : 0u) << 24;
            *(unsigned*)(sM + suN * PLF + ro) = mw;
            // CP(z): same thread wrote m(z+1) here -> use mw directly (no hazard)
            const unsigned cpw = mw & *(const unsigned*)(sM + szm * PLF + ro)
                                    & *(const unsigned*)(sM + sz  * PLF + ro);
            *(unsigned*)(sCP + scp * PLF + ro) = cpw;
        }
        __syncthreads();
        // next step writes slots (z+2): u/v/m (z+2)&4-ring and w (z+2)%3 never alias
        // this step's read set {z-1,z,z+1} / {z}; CP (z+1)&1 != z&1 -> one sync ok.

        // ---- consume: 6 output rows, this thread's column x ----
        if (x >= 1 && x <= Wn - 2) {
            #pragma unroll
            for (int r = 1; r <= TY; ++r) {
                const int y = y0 - 1 + r;
                if (y > Hn - 2) break;
                const unsigned char* cp = sCP + scp * PLF;
                const int ok = (int)cp[(r - 1) * Wn + x - 1] & cp[(r - 1) * Wn + x]
                             & cp[(r - 1) * Wn + x + 1]
                             & cp[r * Wn + x - 1] & cp[r * Wn + x] & cp[r * Wn + x + 1]
                             & cp[(r + 1) * Wn + x - 1] & cp[(r + 1) * Wn + x]
                             & cp[(r + 1) * Wn + x + 1];

                const float dyU = sU[sz * PLF + (r + 1) * Wn + x] - sU[sz * PLF + (r - 1) * Wn + x];
                const float dzU = sU[suN * PLF + r * Wn + x]      - sU[szm * PLF + r * Wn + x];
                const float dyW = sW[swz * PLF + (r + 1) * Wn + x] - sW[swz * PLF + (r - 1) * Wn + x];
                const float dxW = sW[swz * PLF + r * Wn + x + 1]   - sW[swz * PLF + r * Wn + x - 1];
                const float dxV = sV[sz * PLF + r * Wn + x + 1]    - sV[sz * PLF + r * Wn + x - 1];
                const float dzV = sV[suN * PLF + r * Wn + x]       - sV[szm * PLF + r * Wn + x];

                const float ox = dyW - dzV;
                const float oy = dzU - dxW;
                const float oz = dxV - dyU;
                fs  += (float)ok * sqrtf(ox * ox + oy * oy + oz * oz);
                cnt += ok;
            }
        }
    }

    // ---- block reduction -> unconditional partial ----
    #pragma unroll
    for (int off = 16; off; off >>= 1) {
        fs  += __shfl_down_sync(0xffffffffu, fs,  off);
        cnt += __shfl_down_sync(0xffffffffu, cnt, off);
    }
    __shared__ float ws[8];
    __shared__ int   wc[8];
    const int wid = tid >> 5, lid = tid & 31;
    if (lid == 0) { ws[wid] = fs; wc[wid] = cnt; }
    __syncthreads();
    if (wid == 0) {
        fs  = (lid < 8) ? ws[lid] : 0.f;
        cnt = (lid < 8) ? wc[lid] : 0;
        #pragma unroll
        for (int off = 4; off; off >>= 1) {
            fs  += __shfl_down_sync(0xffffffffu, fs,  off);
            cnt += __shfl_down_sync(0xffffffffu, cnt, off);
        }
        if (lid == 0) {
            const int slot = blockIdx.y * NYT + blockIdx.x;
            g_psum[slot] = fs;
            g_pcnt[slot] = (unsigned)cnt;
        }
    }
}

__global__ __launch_bounds__(1024)
void k_final(float* __restrict__ out) {
    const int tid = threadIdx.x;
    double             s = 0.0;
    unsigned long long c = 0ull;
    for (int i = tid; i < NBLK; i += 1024) {
        s += (double)g_psum[i];
        c += (unsigned long long)g_pcnt[i];
    }
    #pragma unroll
    for (int off = 16; off; off >>= 1) {
        s += __shfl_down_sync(0xffffffffu, s, off);
        c += __shfl_down_sync(0xffffffffu, c, off);
    }
    __shared__ double             ds[32];
    __shared__ unsigned long long dc[32];
    const int wid = tid >> 5, lid = tid & 31;
    if (lid == 0) { ds[wid] = s; dc[wid] = c; }
    __syncthreads();
    if (wid == 0) {
        s = (lid < 32) ? ds[lid] : 0.0;
        c = (lid < 32) ? dc[lid] : 0ull;
        #pragma unroll
        for (int off = 16; off; off >>= 1) {
            s += __shfl_down_sync(0xffffffffu, s, off);
            c += __shfl_down_sync(0xffffffffu, c, off);
        }
        if (lid == 0) out[0] = (float)(s / (double)c);
    }
}

extern "C" void kernel_launch(void* const* d_in, const int* in_sizes, int n_in,
                              void* d_out, int out_size) {
    const float* P = (const float*)d_in[0];
    const float* T = (const float*)d_in[1];
    const float* M = (const float*)d_in[2];
    float*       O = (float*)d_out;

    cudaFuncSetAttribute(k_main, cudaFuncAttributeMaxDynamicSharedMemorySize, SMEM_BYTES);
    k_main<<<dim3(NYT, 2 * ZC), 256, SMEM_BYTES>>>(P, T, M);
    k_final<<<1, 1024>>>(O);
}

// round 9
// speedup vs baseline: 2.0006x; 1.3670x over previous
#include <cuda_runtime.h>
#include <math.h>

// predicts/targets (2,4,64,256,256) f32, masks (2,1,64,256,256) f32 -> scalar f32.
// Identities (validated R2..R7, rel_err ~1e-7):
//   omega_pred - omega_trgt = vorticity(scale*(P-T));  scale/(2*delta)=1
//   voxel counts & contributes <=> all 27 masks in 3x3x3 neighborhood == 1
namespace {
constexpr int Bn = 2, Cn = 4, Dn = 64, Hn = 256, Wn = 256;
constexpr long long CH = (long long)Dn * Hn * Wn;
constexpr int TY  = 7;                   // output rows per block
constexpr int RWS = 9;                   // staged rows (TY + 2 halo)
constexpr int NYT = 37;                  // 37*7 = 259 >= 254
constexpr int ZC  = 4;                   // z-chunks per batch (16,16,16,14)
constexpr int NBLK = NYT * 2 * ZC;       // 296 = 2 blocks/SM * 148 SMs exactly
constexpr int PLF  = RWS * Wn;           // elems per staged plane (2304)
constexpr int NF4  = PLF / 4;            // 576 float4 slots per plane
// dynamic smem layout (bytes)
constexpr int OFF_U  = 0;                       // 3 f32 planes (z-ring)
constexpr int OFF_V  = OFF_U  + 3 * PLF * 4;
constexpr int OFF_W  = OFF_V  + 3 * PLF * 4;
constexpr int OFF_M  = OFF_W  + 3 * PLF * 4;    // 3 u8 planes (mask 0/1 bytes)
constexpr int OFF_CP = OFF_M  + 3 * PLF;        // 2 u8 planes (3z column AND)
constexpr int SMEM_BYTES = OFF_CP + 2 * PLF;    // 94464 B -> 2 blocks/SM
}

__device__ float        g_psum[NBLK];
__device__ unsigned int g_pcnt[NBLK];

__global__ __launch_bounds__(512, 2)
void k_main(const float* __restrict__ P,
            const float* __restrict__ T,
            const float* __restrict__ M) {
    extern __shared__ unsigned char smem[];
    float*         sU  = (float*)(smem + OFF_U);
    float*         sV  = (float*)(smem + OFF_V);
    float*         sW  = (float*)(smem + OFF_W);
    unsigned char* sM  = smem + OFF_M;
    unsigned char* sCP = smem + OFF_CP;

    const int tid  = threadIdx.x;
    const int x    = tid & 255;
    const int half = tid >> 8;                    // 0..1
    const int b    = blockIdx.y / ZC;
    const int zi   = blockIdx.y % ZC;
    const int z0   = 1 + zi * 16;
    const int z1   = min(z0 + 15, Dn - 2);        // chunks: 16,16,16,14
    const int y0   = 1 + blockIdx.x * TY;

    const float* mb = M + (long long)b * CH;
    const float* uP = P + ((long long)b * Cn + 1) * CH;
    const float* uT = T + ((long long)b * Cn + 1) * CH;
    const float* vP = uP + CH;  const float* vT = uT + CH;
    const float* wP = vP + CH;  const float* wT = vT + CH;

    // ---- prologue: planes z0-1, z0 of u,v,m ; plane z0 of w ----
    #pragma unroll
    for (int k = 0; k < 2; ++k) {
        const int zz = z0 - 1 + k;
        const int sf = zz % 3;
        #pragma unroll
        for (int i = 0; i < 2; ++i) {
            const int idx = (i << 9) | tid;
            if (idx < NF4) {
                const int r  = idx >> 6;
                const int x4 = (idx & 63) << 2;
                const int yy = min(y0 - 1 + r, Hn - 1);
                const long long base = ((long long)zz * Hn + yy) * Wn + x4;
                const int o = sf * PLF + r * Wn + x4;

                float4 a = *(const float4*)(uP + base);
                float4 c = *(const float4*)(uT + base);
                *(float4*)(sU + o) = make_float4(a.x - c.x, a.y - c.y, a.z - c.z, a.w - c.w);
                a = *(const float4*)(vP + base);
                c = *(const float4*)(vT + base);
                *(float4*)(sV + o) = make_float4(a.x - c.x, a.y - c.y, a.z - c.z, a.w - c.w);
                if (k == 1) {
                    a = *(const float4*)(wP + base);
                    c = *(const float4*)(wT + base);
                    *(float4*)(sW + o) = make_float4(a.x - c.x, a.y - c.y, a.z - c.z, a.w - c.w);
                }
                const float4 mv = *(const float4*)(mb + base);
                const unsigned mw = (mv.x > 0.5f ? 1u : 0u)
                                  | (mv.y > 0.5f ? 1u : 0u) << 8
                                  | (mv.z > 0.5f ? 1u : 0u) << 16
                                  | (mv.w > 0.5f ? 1u : 0u) << 24;
                *(unsigned*)(sM + o) = mw;
            }
        }
    }
    __syncthreads();

    float fs  = 0.f;
    int   cnt = 0;
    const int rlo = (half == 0) ? 1 : 5;          // rows 1..4 / 5..7
    const int rhi = (half == 0) ? 4 : 7;

    for (int z = z0; z <= z1; ++z) {
        const int snew = (z + 1) % 3;
        const int szm  = (z - 1) % 3, sz = z % 3;
        const int scp  = z & 1;

        // ---- stage plane z+1 (u,v,w,m) and compute CP(z) = AND m(z-1..z+1) ----
        #pragma unroll
        for (int i = 0; i < 2; ++i) {
            const int idx = (i << 9) | tid;
            if (idx < NF4) {
                const int r  = idx >> 6;
                const int x4 = (idx & 63) << 2;
                const int yy = min(y0 - 1 + r, Hn - 1);
                const long long base = ((long long)(z + 1) * Hn + yy) * Wn + x4;
                const int ro = r * Wn + x4;

                float4 a = *(const float4*)(uP + base);
                float4 c = *(const float4*)(uT + base);
                *(float4*)(sU + snew * PLF + ro) = make_float4(a.x - c.x, a.y - c.y, a.z - c.z, a.w - c.w);
                a = *(const float4*)(vP + base);
                c = *(const float4*)(vT + base);
                *(float4*)(sV + snew * PLF + ro) = make_float4(a.x - c.x, a.y - c.y, a.z - c.z, a.w - c.w);
                a = *(const float4*)(wP + base);
                c = *(const float4*)(wT + base);
                *(float4*)(sW + snew * PLF + ro) = make_float4(a.x - c.x, a.y - c.y, a.z - c.z, a.w - c.w);

                const float4 mv = *(const float4*)(mb + base);
                const unsigned mw = (mv.x > 0.5f ? 1u : 0u)
                                  | (mv.y > 0.5f ? 1u : 0u) << 8
                                  | (mv.z > 0.5f ? 1u : 0u) << 16
                                  | (mv.w > 0.5f ? 1u : 0u) << 24;
                *(unsigned*)(sM + snew * PLF + ro) = mw;
                // m(z-1), m(z) were written >=1 sync ago; m(z+1) is mw (this thread)
                const unsigned cpw = mw & *(const unsigned*)(sM + szm * PLF + ro)
                                        & *(const unsigned*)(sM + sz  * PLF + ro);
                *(unsigned*)(sCP + scp * PLF + ro) = cpw;
            }
        }
        __syncthreads();

        // ---- consume plane z: half 0 -> rows 1..4, half 1 -> rows 5..7 ----
        if (x >= 1 && x <= Wn - 2) {
            const unsigned char* cp = sCP + scp * PLF;
            #pragma unroll
            for (int r = rlo; r <= rhi; ++r) {
                const int y = y0 - 1 + r;
                if (y > Hn - 2) break;
                const int ok = (int)cp[(r - 1) * Wn + x - 1] & cp[(r - 1) * Wn + x]
                             & cp[(r - 1) * Wn + x + 1]
                             & cp[r * Wn + x - 1] & cp[r * Wn + x] & cp[r * Wn + x + 1]
                             & cp[(r + 1) * Wn + x - 1] & cp[(r + 1) * Wn + x]
                             & cp[(r + 1) * Wn + x + 1];

                const float dyU = sU[sz * PLF + (r + 1) * Wn + x] - sU[sz * PLF + (r - 1) * Wn + x];
                const float dzU = sU[snew * PLF + r * Wn + x]     - sU[szm * PLF + r * Wn + x];
                const float dyW = sW[sz * PLF + (r + 1) * Wn + x] - sW[sz * PLF + (r - 1) * Wn + x];
                const float dxW = sW[sz * PLF + r * Wn + x + 1]   - sW[sz * PLF + r * Wn + x - 1];
                const float dxV = sV[sz * PLF + r * Wn + x + 1]   - sV[sz * PLF + r * Wn + x - 1];
                const float dzV = sV[snew * PLF + r * Wn + x]     - sV[szm * PLF + r * Wn + x];

                const float ox = dyW - dzV;
                const float oy = dzU - dxW;
                const float oz = dxV - dyU;
                fs  += (float)ok * sqrtf(ox * ox + oy * oy + oz * oz);
                cnt += ok;
            }
        }
        __syncthreads();   // depth-3 rings: next stage overwrites slot (z-1)%3
    }

    // ---- block reduction (16 warps) -> unconditional partial ----
    #pragma unroll
    for (int off = 16; off; off >>= 1) {
        fs  += __shfl_down_sync(0xffffffffu, fs,  off);
        cnt += __shfl_down_sync(0xffffffffu, cnt, off);
    }
    __shared__ float ws[16];
    __shared__ int   wc[16];
    const int wid = tid >> 5, lid = tid & 31;
    if (lid == 0) { ws[wid] = fs; wc[wid] = cnt; }
    __syncthreads();
    if (wid == 0) {
        fs  = (lid < 16) ? ws[lid] : 0.f;
        cnt = (lid < 16) ? wc[lid] : 0;
        #pragma unroll
        for (int off = 8; off; off >>= 1) {
            fs  += __shfl_down_sync(0xffffffffu, fs,  off);
            cnt += __shfl_down_sync(0xffffffffu, cnt, off);
        }
        if (lid == 0) {
            const int slot = blockIdx.y * NYT + blockIdx.x;
            g_psum[slot] = fs;
            g_pcnt[slot] = (unsigned)cnt;
        }
    }
}

__global__ __launch_bounds__(1024)
void k_final(float* __restrict__ out) {
    const int tid = threadIdx.x;
    double             s = 0.0;
    unsigned long long c = 0ull;
    for (int i = tid; i < NBLK; i += 1024) {
        s += (double)g_psum[i];
        c += (unsigned long long)g_pcnt[i];
    }
    #pragma unroll
    for (int off = 16; off; off >>= 1) {
        s += __shfl_down_sync(0xffffffffu, s, off);
        c += __shfl_down_sync(0xffffffffu, c, off);
    }
    __shared__ double             ds[32];
    __shared__ unsigned long long dc[32];
    const int wid = tid >> 5, lid = tid & 31;
    if (lid == 0) { ds[wid] = s; dc[wid] = c; }
    __syncthreads();
    if (wid == 0) {
        s = (lid < 32) ? ds[lid] : 0.0;
        c = (lid < 32) ? dc[lid] : 0ull;
        #pragma unroll
        for (int off = 16; off; off >>= 1) {
            s += __shfl_down_sync(0xffffffffu, s, off);
            c += __shfl_down_sync(0xffffffffu, c, off);
        }
        if (lid == 0) out[0] = (float)(s / (double)c);
    }
}

extern "C" void kernel_launch(void* const* d_in, const int* in_sizes, int n_in,
                              void* d_out, int out_size) {
    const float* P = (const float*)d_in[0];
    const float* T = (const float*)d_in[1];
    const float* M = (const float*)d_in[2];
    float*       O = (float*)d_out;

    cudaFuncSetAttribute(k_main, cudaFuncAttributeMaxDynamicSharedMemorySize, SMEM_BYTES);
    k_main<<<dim3(NYT, 2 * ZC), 512, SMEM_BYTES>>>(P, T, M);
    k_final<<<1, 1024>>>(O);
}

// round 10
// speedup vs baseline: 2.0308x; 1.0151x over previous
#include <cuda_runtime.h>
#include <math.h>

// predicts/targets (2,4,64,256,256) f32, masks (2,1,64,256,256) f32 -> scalar f32.
// Identities (validated R2..R8, rel_err ~1e-7):
//   omega_pred - omega_trgt = vorticity(scale*(P-T));  scale/(2*delta)=1
//   voxel counts & contributes <=> all 27 masks in 3x3x3 neighborhood == 1
namespace {
constexpr int Bn = 2, Cn = 4, Dn = 64, Hn = 256, Wn = 256;
constexpr long long CH = (long long)Dn * Hn * Wn;
constexpr int TY  = 7;                   // output rows per block
constexpr int RWS = 9;                   // staged rows (TY + 2 halo)
constexpr int NYT = 37;                  // 37*7 = 259 >= 254
constexpr int ZC  = 4;                   // z-chunks per batch (16,16,16,14)
constexpr int NBLK = NYT * 2 * ZC;       // 296 = 2 blocks/SM * 148 SMs exactly
constexpr int PLF  = RWS * Wn;           // elems per staged plane (2304)
constexpr int NF4  = PLF / 4;            // 576 float4 slots per plane
// dynamic smem layout (bytes)
constexpr int OFF_U  = 0;                       // 3 f32 planes (z-ring)
constexpr int OFF_V  = OFF_U  + 3 * PLF * 4;    // 3 f32 planes
constexpr int OFF_W  = OFF_V  + 3 * PLF * 4;    // 2 f32 planes (consume z reads only w(z))
constexpr int OFF_M  = OFF_W  + 2 * PLF * 4;    // 3 u8 planes (mask 0/1 bytes)
constexpr int OFF_CP = OFF_M  + 3 * PLF;        // 2 u8 planes (3z column AND)
constexpr int SMEM_BYTES = OFF_CP + 2 * PLF;    // 85248 B -> 2 blocks/SM
}

__device__ float        g_psum[NBLK];
__device__ unsigned int g_pcnt[NBLK];
__device__ unsigned int g_ticket = 0;    // completion counter; reset by last block

__global__ __launch_bounds__(512, 2)
void k_main(const float* __restrict__ P,
            const float* __restrict__ T,
            const float* __restrict__ M,
            float* __restrict__ out) {
    extern __shared__ unsigned char smem[];
    float*         sU  = (float*)(smem + OFF_U);
    float*         sV  = (float*)(smem + OFF_V);
    float*         sW  = (float*)(smem + OFF_W);
    unsigned char* sM  = smem + OFF_M;
    unsigned char* sCP = smem + OFF_CP;

    const int tid  = threadIdx.x;
    const int x    = tid & 255;
    const int half = tid >> 8;                    // 0..1
    const int b    = blockIdx.y / ZC;
    const int zi   = blockIdx.y % ZC;
    const int z0   = 1 + zi * 16;
    const int z1   = min(z0 + 15, Dn - 2);        // chunks: 16,16,16,14
    const int y0   = 1 + blockIdx.x * TY;

    const float* mb = M + (long long)b * CH;
    const float* uP = P + ((long long)b * Cn + 1) * CH;
    const float* uT = T + ((long long)b * Cn + 1) * CH;
    const float* vP = uP + CH;  const float* vT = uT + CH;
    const float* wP = vP + CH;  const float* wT = vT + CH;

    // ---- prologue: planes z0-1, z0 of u,v,m ; plane z0 of w ----
    #pragma unroll
    for (int k = 0; k < 2; ++k) {
        const int zz = z0 - 1 + k;
        const int sf = zz % 3;
        #pragma unroll
        for (int i = 0; i < 2; ++i) {
            const int idx = (i << 9) | tid;
            if (idx < NF4) {
                const int r  = idx >> 6;
                const int x4 = (idx & 63) << 2;
                const int yy = min(y0 - 1 + r, Hn - 1);
                const long long base = ((long long)zz * Hn + yy) * Wn + x4;
                const int o = sf * PLF + r * Wn + x4;

                float4 a = *(const float4*)(uP + base);
                float4 c = *(const float4*)(uT + base);
                *(float4*)(sU + o) = make_float4(a.x - c.x, a.y - c.y, a.z - c.z, a.w - c.w);
                a = *(const float4*)(vP + base);
                c = *(const float4*)(vT + base);
                *(float4*)(sV + o) = make_float4(a.x - c.x, a.y - c.y, a.z - c.z, a.w - c.w);
                if (k == 1) {
                    a = *(const float4*)(wP + base);
                    c = *(const float4*)(wT + base);
                    *(float4*)(sW + ((zz & 1) * PLF) + r * Wn + x4)
                        = make_float4(a.x - c.x, a.y - c.y, a.z - c.z, a.w - c.w);
                }
                const float4 mv = *(const float4*)(mb + base);
                const unsigned mw = (mv.x > 0.5f ? 1u : 0u)
                                  | (mv.y > 0.5f ? 1u : 0u) << 8
                                  | (mv.z > 0.5f ? 1u : 0u) << 16
                                  | (mv.w > 0.5f ? 1u : 0u) << 24;
                *(unsigned*)(sM + o) = mw;
            }
        }
    }
    __syncthreads();

    float fs  = 0.f;
    int   cnt = 0;
    const int rlo = (half == 0) ? 1 : 5;          // rows 1..4 / 5..7
    const int rhi = (half == 0) ? 4 : 7;

    for (int z = z0; z <= z1; ++z) {
        const int snew = (z + 1) % 3;
        const int szm  = (z - 1) % 3, sz = z % 3;
        const int swz  = z & 1, swN = (z + 1) & 1;
        const int scp  = z & 1;

        // ---- stage plane z+1 (u,v,w,m) and compute CP(z) = AND m(z-1..z+1) ----
        #pragma unroll
        for (int i = 0; i < 2; ++i) {
            const int idx = (i << 9) | tid;
            if (idx < NF4) {
                const int r  = idx >> 6;
                const int x4 = (idx & 63) << 2;
                const int yy = min(y0 - 1 + r, Hn - 1);
                const long long base = ((long long)(z + 1) * Hn + yy) * Wn + x4;
                const int ro = r * Wn + x4;

                float4 a = *(const float4*)(uP + base);
                float4 c = *(const float4*)(uT + base);
                *(float4*)(sU + snew * PLF + ro) = make_float4(a.x - c.x, a.y - c.y, a.z - c.z, a.w - c.w);
                a = *(const float4*)(vP + base);
                c = *(const float4*)(vT + base);
                *(float4*)(sV + snew * PLF + ro) = make_float4(a.x - c.x, a.y - c.y, a.z - c.z, a.w - c.w);
                a = *(const float4*)(wP + base);
                c = *(const float4*)(wT + base);
                *(float4*)(sW + swN * PLF + ro) = make_float4(a.x - c.x, a.y - c.y, a.z - c.z, a.w - c.w);

                const float4 mv = *(const float4*)(mb + base);
                const unsigned mw = (mv.x > 0.5f ? 1u : 0u)
                                  | (mv.y > 0.5f ? 1u : 0u) << 8
                                  | (mv.z > 0.5f ? 1u : 0u) << 16
                                  | (mv.w > 0.5f ? 1u : 0u) << 24;
                *(unsigned*)(sM + snew * PLF + ro) = mw;
                // m(z-1), m(z) written >=1 sync ago; m(z+1) is mw (this thread)
                const unsigned cpw = mw & *(const unsigned*)(sM + szm * PLF + ro)
                                        & *(const unsigned*)(sM + sz  * PLF + ro);
                *(unsigned*)(sCP + scp * PLF + ro) = cpw;
            }
        }
        __syncthreads();

        // ---- consume plane z: half 0 -> rows 1..4, half 1 -> rows 5..7 ----
        if (x >= 1 && x <= Wn - 2) {
            const unsigned char* cp = sCP + scp * PLF;
            #pragma unroll
            for (int r = rlo; r <= rhi; ++r) {
                const int y = y0 - 1 + r;
                if (y > Hn - 2) break;
                const int ok = (int)cp[(r - 1) * Wn + x - 1] & cp[(r - 1) * Wn + x]
                             & cp[(r - 1) * Wn + x + 1]
                             & cp[r * Wn + x - 1] & cp[r * Wn + x] & cp[r * Wn + x + 1]
                             & cp[(r + 1) * Wn + x - 1] & cp[(r + 1) * Wn + x]
                             & cp[(r + 1) * Wn + x + 1];

                const float dyU = sU[sz * PLF + (r + 1) * Wn + x] - sU[sz * PLF + (r - 1) * Wn + x];
                const float dzU = sU[snew * PLF + r * Wn + x]     - sU[szm * PLF + r * Wn + x];
                const float dyW = sW[swz * PLF + (r + 1) * Wn + x] - sW[swz * PLF + (r - 1) * Wn + x];
                const float dxW = sW[swz * PLF + r * Wn + x + 1]   - sW[swz * PLF + r * Wn + x - 1];
                const float dxV = sV[sz * PLF + r * Wn + x + 1]    - sV[sz * PLF + r * Wn + x - 1];
                const float dzV = sV[snew * PLF + r * Wn + x]      - sV[szm * PLF + r * Wn + x];

                const float ox = dyW - dzV;
                const float oy = dzU - dxW;
                const float oz = dxV - dyU;
                fs  += (float)ok * sqrtf(ox * ox + oy * oy + oz * oz);
                cnt += ok;
            }
        }
        __syncthreads();   // next stage overwrites u/v/m slot (z-1)%3 and w slot z&1
    }

    // ---- block reduction (16 warps) -> partial, then last block finalizes ----
    #pragma unroll
    for (int off = 16; off; off >>= 1) {
        fs  += __shfl_down_sync(0xffffffffu, fs,  off);
        cnt += __shfl_down_sync(0xffffffffu, cnt, off);
    }
    __shared__ float ws[16];
    __shared__ int   wc[16];
    __shared__ bool  sLast;
    const int wid = tid >> 5, lid = tid & 31;
    if (lid == 0) { ws[wid] = fs; wc[wid] = cnt; }
    __syncthreads();
    if (wid == 0) {
        fs  = (lid < 16) ? ws[lid] : 0.f;
        cnt = (lid < 16) ? wc[lid] : 0;
        #pragma unroll
        for (int off = 8; off; off >>= 1) {
            fs  += __shfl_down_sync(0xffffffffu, fs,  off);
            cnt += __shfl_down_sync(0xffffffffu, cnt, off);
        }
        if (lid == 0) {
            const int slot = blockIdx.y * NYT + blockIdx.x;
            g_psum[slot] = fs;
            g_pcnt[slot] = (unsigned)cnt;
            __threadfence();                               // partials visible before ticket
            const unsigned t = atomicAdd(&g_ticket, 1u);
            sLast = (t == NBLK - 1);
        }
    }
    __syncthreads();

    if (sLast) {
        // Deterministic final reduce: fixed order over 296 slots, double accum.
        double             s = (tid < NBLK) ? (double)__ldcg(&g_psum[tid]) : 0.0;
        unsigned long long c = (tid < NBLK) ? (unsigned long long)__ldcg(&g_pcnt[tid]) : 0ull;
        #pragma unroll
        for (int off = 16; off; off >>= 1) {
            s += __shfl_down_sync(0xffffffffu, s, off);
            c += __shfl_down_sync(0xffffffffu, c, off);
        }
        __shared__ double             ds[16];
        __shared__ unsigned long long dc[16];
        if (lid == 0) { ds[wid] = s; dc[wid] = c; }
        __syncthreads();
        if (wid == 0) {
            s = (lid < 16) ? ds[lid] : 0.0;
            c = (lid < 16) ? dc[lid] : 0ull;
            #pragma unroll
            for (int off = 8; off; off >>= 1) {
                s += __shfl_down_sync(0xffffffffu, s, off);
                c += __shfl_down_sync(0xffffffffu, c, off);
            }
            if (lid == 0) {
                out[0] = (float)(s / (double)c);
                g_ticket = 0;                              // reset for next graph replay
            }
        }
    }
}

extern "C" void kernel_launch(void* const* d_in, const int* in_sizes, int n_in,
                              void* d_out, int out_size) {
    const float* P = (const float*)d_in[0];
    const float* T = (const float*)d_in[1];
    const float* M = (const float*)d_in[2];
    float*       O = (float*)d_out;

    cudaFuncSetAttribute(k_main, cudaFuncAttributeMaxDynamicSharedMemorySize, SMEM_BYTES);
    k_main<<<dim3(NYT, 2 * ZC), 512, SMEM_BYTES>>>(P, T, M, O);
}